// round 5
// baseline (speedup 1.0000x reference)
#include <cuda_runtime.h>
#include <cstdint>
#include <math.h>

#define BB 2048
#define NN 200
#define HH 128
#define TT 180

__device__ float g_G[HH * HH];     // G[h][k] = sum_o W[o][h] W[o][k]  (symmetric)
__device__ float g_C[HH];          // c[h]    = sum_o W[o][h] b[o]
__device__ float g_V0[BB * HH];    // V0[b]   = G x[b,0] + c

__device__ __forceinline__ float neg_inf() { return __int_as_float(0xff800000); }

__global__ void k_zero(float* __restrict__ out, int n) {
    int i = blockIdx.x * blockDim.x + threadIdx.x;
    if (i < n) out[i] = 0.0f;
}

// ---- G = W^T W, c = W^T b.  64 CTAs x 256 thr, one G element per thread. ----
__global__ void k_gc(const float* __restrict__ W, const float* __restrict__ bias) {
    int e = blockIdx.x * 256 + threadIdx.x;       // e = h*128 + k
    int h = e >> 7, k = e & 127;
    float acc = 0.f;
    #pragma unroll 8
    for (int o = 0; o < HH; o++)
        acc = fmaf(W[o * HH + h], W[o * HH + k], acc);
    g_G[e] = acc;
    if (e < HH) {
        float a = 0.f;
        #pragma unroll 8
        for (int o = 0; o < HH; o++)
            a = fmaf(W[o * HH + e], bias[o], a);
        g_C[e] = a;
    }
}

// ---- V0[b] = G x[b,0] + c.  128 CTAs x 128 thr, 16 batches per CTA. ----
__global__ void __launch_bounds__(128) k_v0(const float* __restrict__ x) {
    __shared__ float xs[16][HH];
    int tid = threadIdx.x;
    int b0 = blockIdx.x * 16;
    for (int idx = tid; idx < 16 * HH; idx += 128) {
        int r = idx >> 7, k = idx & 127;
        xs[r][k] = x[(size_t)(b0 + r) * NN * HH + k];
    }
    __syncthreads();
    int h = tid;
    float acc[16];
    float c = g_C[h];
    #pragma unroll
    for (int j = 0; j < 16; j++) acc[j] = c;
    for (int k = 0; k < HH; k++) {
        float g = g_G[k * HH + h];                 // coalesced (symmetric)
        #pragma unroll
        for (int j = 0; j < 16; j++)
            acc[j] = fmaf(g, xs[j][k], acc[j]);
    }
    #pragma unroll
    for (int j = 0; j < 16; j++)
        g_V0[(size_t)(b0 + j) * HH + h] = acc[j];
}

// ---- routing: stream x from GMEM (warp-per-node), no W work on fast path ----
__global__ void __launch_bounds__(256, 4)
k_route(const float* __restrict__ x, const float* __restrict__ coords,
        const float* __restrict__ demands, const float* __restrict__ capacity,
        const int* __restrict__ nsteps, float* __restrict__ out) {
    __shared__ float cx[NN], cy[NN], dem[NN], vsm[HH], xrow[HH];
    __shared__ int vis[NN];
    __shared__ float red[8];
    __shared__ int redi[8], nxt_s;

    const int tid  = threadIdx.x;
    const int b    = blockIdx.x;
    const int lane = tid & 31;
    const int wid  = tid >> 5;

    // prologue
    {
        const float2* cb2 = (const float2*)(coords + (size_t)b * NN * 2);
        const float*  db  = demands + (size_t)b * NN;
        if (tid < NN) {
            float2 c2 = cb2[tid];
            cx[tid] = c2.x; cy[tid] = c2.y;
            dem[tid] = db[tid];
            vis[tid] = 0;
        }
        if (tid < HH) vsm[tid] = g_V0[(size_t)b * HH + tid];
    }
    __syncthreads();

    const int T = nsteps ? nsteps[0] : TT;
    const float cap = capacity[b];
    float rem = cap;
    int cur = 0;
    const float* xb = x + (size_t)b * NN * HH;

    for (int step = 0; step < T; step++) {
        float4 vreg = *(const float4*)(vsm + lane * 4);
        float cxc = cx[cur], cyc = cy[cur];
        float best = neg_inf();
        int bidx = 0;
        // warp w handles nodes n = w, w+8, ... (ascending -> first-index tiebreak)
        #pragma unroll 5
        for (int k = 0; k < 25; k++) {
            int n = wid + 8 * k;
            float4 xr = *(const float4*)(xb + (size_t)n * HH + lane * 4);
            float p = fmaf(xr.x, vreg.x, fmaf(xr.y, vreg.y,
                      fmaf(xr.z, vreg.z, xr.w * vreg.w)));
            #pragma unroll
            for (int off = 16; off > 0; off >>= 1)
                p += __shfl_xor_sync(0xffffffffu, p, off);
            float dx = cx[n] - cxc, dy = cy[n] - cyc;
            float s = p - 0.1f * sqrtf(dx * dx + dy * dy);
            if (n != 0 && (vis[n] || (dem[n] > rem))) s = neg_inf();
            if (s > best) { best = s; bidx = n; }    // strictly greater: keeps lowest n
        }
        if (lane == 0) { red[wid] = best; redi[wid] = bidx; }
        __syncthreads();
        if (tid == 0) {
            float Bv = red[0]; int Bi = redi[0];
            #pragma unroll
            for (int w = 1; w < 8; w++) {
                float v = red[w]; int i2 = redi[w];
                if (v > Bv || (v == Bv && i2 < Bi)) { Bv = v; Bi = i2; }
            }
            nxt_s = Bi;
            vis[Bi] = 1;
            out[(size_t)b * T + step] = (float)Bi;
        }
        __syncthreads();
        int nxt = nxt_s;
        rem = (nxt == 0) ? cap : (rem - dem[nxt]);
        int prev = cur;
        cur = nxt;
        // depot fixed point: identical state recurs -> all remaining actions are 0
        // and the output buffer is pre-zeroed. Exact, not approximate.
        if (prev == 0 && nxt == 0) break;

        // live path (rare): v = G x_cur + c
        if (tid < 32) {
            float4 xc = *(const float4*)(xb + (size_t)cur * HH + tid * 4);
            *(float4*)(xrow + tid * 4) = xc;
        }
        __syncthreads();
        if (tid < HH) {
            float acc = g_C[tid];
            #pragma unroll 8
            for (int k = 0; k < HH; k++)
                acc = fmaf(g_G[k * HH + tid], xrow[k], acc);
            vsm[tid] = acc;
        }
        __syncthreads();
    }
}

extern "C" void kernel_launch(void* const* d_in, const int* in_sizes, int n_in,
                              void* d_out, int out_size) {
    const float* x        = (const float*)d_in[0];
    const float* W        = (const float*)d_in[1];
    const float* bias     = (const float*)d_in[2];
    const float* coords   = (const float*)d_in[3];
    const float* demands  = (const float*)d_in[4];
    const float* capacity = (const float*)d_in[5];
    const int*   nsteps   = (n_in > 6) ? (const int*)d_in[6] : nullptr;
    float* out = (float*)d_out;

    int zgrid = (out_size + 255) / 256;
    k_zero<<<zgrid, 256>>>(out, out_size);
    k_gc<<<HH * HH / 256, 256>>>(W, bias);
    k_v0<<<BB / 16, 128>>>(x);
    k_route<<<BB, 256>>>(x, coords, demands, capacity, nsteps, out);
}

// round 8
// speedup vs baseline: 1.3341x; 1.3341x over previous
#include <cuda_runtime.h>
#include <cstdint>
#include <math.h>

#define BB 2048
#define NN 200
#define HH 128
#define TT 180

__device__ float g_V0[BB * HH];   // V0[b] = W^T (W x[b,0] + bias)

__device__ __forceinline__ float neg_inf() { return __int_as_float(0xff800000); }

// ---- one aux kernel: zero out[] (grid-stride) + V0 for all batches ----------
// 128 CTAs x 256 threads, 16 batches per CTA, W staged in dynamic smem.
#define WS_OFF 0                   // [128][132] W rows, pad 132 (f4-aligned, conflict-free)
#define XS_OFF 16896               // [16][128]
#define QS_OFF 18944               // [16][128]
#define BS_OFF 20992               // [128]
#define V0_SMEM_FLOATS 21120
#define V0_SMEM_BYTES (V0_SMEM_FLOATS * 4)

__global__ void __launch_bounds__(256, 1)
k_v0(const float* __restrict__ x, const float* __restrict__ W,
     const float* __restrict__ bias, float* __restrict__ out, int out_size) {
    extern __shared__ float sm[];
    const int tid = threadIdx.x;
    const int b0 = blockIdx.x * 16;

    // zero the output buffer (layout-agnostic grid-stride)
    for (int i = blockIdx.x * 256 + tid; i < out_size; i += gridDim.x * 256)
        out[i] = 0.0f;

    // stage W (coalesced f4), bias, 16 x0 rows
    for (int idx = tid; idx < HH * 32; idx += 256) {
        int o = idx >> 5, j = idx & 31;
        *(float4*)(sm + WS_OFF + o * 132 + j * 4) = ((const float4*)W)[idx];
    }
    if (tid < HH) sm[BS_OFF + tid] = bias[tid];
    for (int idx = tid; idx < 16 * 32; idx += 256) {
        int r = idx >> 5, j = idx & 31;
        *(float4*)(sm + XS_OFF + r * HH + j * 4) =
            *(const float4*)(x + (size_t)(b0 + r) * NN * HH + j * 4);
    }
    __syncthreads();

    // phase 1: Q[j][o] = sum_h W[o][h] x0[j][h] + bias[o]
    {
        const int o = tid & 127, jb = (tid >> 7) * 8;
        float acc[8];
        float bo = sm[BS_OFF + o];
        #pragma unroll
        for (int j = 0; j < 8; j++) acc[j] = bo;
        for (int h = 0; h < HH; h += 4) {
            float4 w4 = *(const float4*)(sm + WS_OFF + o * 132 + h);
            #pragma unroll
            for (int j = 0; j < 8; j++) {
                float4 xv = *(const float4*)(sm + XS_OFF + (jb + j) * HH + h);
                acc[j] = fmaf(w4.x, xv.x, fmaf(w4.y, xv.y,
                         fmaf(w4.z, xv.z, fmaf(w4.w, xv.w, acc[j]))));
            }
        }
        #pragma unroll
        for (int j = 0; j < 8; j++) sm[QS_OFF + (jb + j) * HH + o] = acc[j];
    }
    __syncthreads();

    // phase 2: V0[j][h] = sum_o W[o][h] Q[j][o]
    {
        const int h = tid & 127, jb = (tid >> 7) * 8;
        float acc[8];
        #pragma unroll
        for (int j = 0; j < 8; j++) acc[j] = 0.f;
        #pragma unroll 4
        for (int o = 0; o < HH; o++) {
            float w = sm[WS_OFF + o * 132 + h];
            #pragma unroll
            for (int j = 0; j < 8; j++)
                acc[j] = fmaf(w, sm[QS_OFF + (jb + j) * HH + o], acc[j]);
        }
        #pragma unroll
        for (int j = 0; j < 8; j++)
            g_V0[(size_t)(b0 + jb + j) * HH + h] = acc[j];
    }
}

// ---- routing: stream x from GMEM; fast path uses precomputed V0 -------------
__global__ void __launch_bounds__(256, 6)
k_route(const float* __restrict__ x, const float* __restrict__ W,
        const float* __restrict__ bias, const float* __restrict__ coords,
        const float* __restrict__ demands, const float* __restrict__ capacity,
        const int* __restrict__ nsteps, float* __restrict__ out) {
    __shared__ float cx[NN], cy[NN], dem[NN];
    __shared__ float vsm[HH], vpart[HH], qsm[HH], xrow[HH];
    __shared__ int vis[NN];
    __shared__ float red[8];
    __shared__ int redi[8], nxt_s;

    const int tid  = threadIdx.x;
    const int b    = blockIdx.x;
    const int lane = tid & 31;
    const int wid  = tid >> 5;

    {
        const float2* cb2 = (const float2*)(coords + (size_t)b * NN * 2);
        const float*  db  = demands + (size_t)b * NN;
        if (tid < NN) {
            float2 c2 = cb2[tid];
            cx[tid] = c2.x; cy[tid] = c2.y;
            dem[tid] = db[tid];
            vis[tid] = 0;
        }
        if (tid < HH) vsm[tid] = g_V0[(size_t)b * HH + tid];
    }
    __syncthreads();

    const int T = nsteps ? nsteps[0] : TT;
    const float cap = capacity[b];
    float rem = cap;
    int cur = 0;
    const float* xb = x + (size_t)b * NN * HH;

    for (int step = 0; step < T; step++) {
        float4 vreg = *(const float4*)(vsm + lane * 4);
        float cxc = cx[cur], cyc = cy[cur];
        float best = neg_inf();
        int bidx = 0;
        // warp w handles nodes n = w, w+8, ... ascending (first-index tiebreak)
        #pragma unroll 5
        for (int k = 0; k < 25; k++) {
            int n = wid + 8 * k;
            float4 xr = *(const float4*)(xb + (size_t)n * HH + lane * 4);
            float p = fmaf(xr.x, vreg.x, fmaf(xr.y, vreg.y,
                      fmaf(xr.z, vreg.z, xr.w * vreg.w)));
            #pragma unroll
            for (int off = 16; off > 0; off >>= 1)
                p += __shfl_xor_sync(0xffffffffu, p, off);
            float dx = cx[n] - cxc, dy = cy[n] - cyc;
            float s = p - 0.1f * sqrtf(dx * dx + dy * dy);
            if (n != 0 && (vis[n] || (dem[n] > rem))) s = neg_inf();
            if (s > best) { best = s; bidx = n; }     // strictly greater: lowest n kept
        }
        if (lane == 0) { red[wid] = best; redi[wid] = bidx; }
        __syncthreads();
        if (tid == 0) {
            float Bv = red[0]; int Bi = redi[0];
            #pragma unroll
            for (int w = 1; w < 8; w++) {
                float v = red[w]; int i2 = redi[w];
                if (v > Bv || (v == Bv && i2 < Bi)) { Bv = v; Bi = i2; }
            }
            nxt_s = Bi;
            vis[Bi] = 1;
            out[(size_t)b * T + step] = (float)Bi;
        }
        __syncthreads();
        int nxt = nxt_s;
        rem = (nxt == 0) ? cap : (rem - dem[nxt]);
        int prev = cur;
        cur = nxt;
        // depot fixed point: identical state recurs -> all remaining actions 0
        // (output pre-zeroed). Exact, not approximate.
        if (prev == 0 && nxt == 0) break;

        // ---- live path (rare): v = W^T (W x_cur + bias) from GMEM W ----------
        if (tid < 32)
            *(float4*)(xrow + tid * 4) = *(const float4*)(xb + (size_t)cur * HH + tid * 4);
        __syncthreads();
        {   // q[o] = W[o,:]·xrow + bias[o], warp-per-row
            float4 xc = *(const float4*)(xrow + lane * 4);
            #pragma unroll
            for (int r = 0; r < 16; r++) {
                int o = wid + r * 8;
                float4 w4 = *(const float4*)(W + (size_t)o * HH + lane * 4);
                float p = fmaf(w4.x, xc.x, fmaf(w4.y, xc.y,
                          fmaf(w4.z, xc.z, w4.w * xc.w)));
                #pragma unroll
                for (int off = 16; off > 0; off >>= 1)
                    p += __shfl_xor_sync(0xffffffffu, p, off);
                if (lane == 0) qsm[o] = p + bias[o];
            }
        }
        __syncthreads();
        {   // v[h] = sum_o W[o][h] q[o], coalesced columns, o split in halves
            int h = tid & 127, half = tid >> 7;
            float acc = 0.f;
            const float* Wp = W + (size_t)(half * 64) * HH + h;
            const float* qp = qsm + half * 64;
            #pragma unroll 8
            for (int o = 0; o < 64; o++)
                acc = fmaf(Wp[(size_t)o * HH], qp[o], acc);
            if (half == 0) vsm[h] = acc; else vpart[h] = acc;
        }
        __syncthreads();
        if (tid < HH) vsm[tid] += vpart[tid];
        __syncthreads();
    }
}

extern "C" void kernel_launch(void* const* d_in, const int* in_sizes, int n_in,
                              void* d_out, int out_size) {
    const float* x        = (const float*)d_in[0];
    const float* W        = (const float*)d_in[1];
    const float* bias     = (const float*)d_in[2];
    const float* coords   = (const float*)d_in[3];
    const float* demands  = (const float*)d_in[4];
    const float* capacity = (const float*)d_in[5];
    const int*   nsteps   = (n_in > 6) ? (const int*)d_in[6] : nullptr;
    float* out = (float*)d_out;

    cudaFuncSetAttribute(k_v0, cudaFuncAttributeMaxDynamicSharedMemorySize, V0_SMEM_BYTES);

    k_v0<<<BB / 16, 256, V0_SMEM_BYTES>>>(x, W, bias, out, out_size);
    k_route<<<BB, 256>>>(x, W, bias, coords, demands, capacity, nsteps, out);
}